// round 16
// baseline (speedup 1.0000x reference)
#include <cuda_runtime.h>
#include <cuda_fp16.h>
#include <cstdint>

typedef unsigned int u32;
typedef unsigned long long u64;
typedef unsigned short u16;

#define HDIM   96
#define NPIX   9216
#define NC     21
#define NROW   24            // padded B rows: 21 classes + ones + 2 zero
#define NB     2
#define KCH    128
#define NCHUNKS (NPIX / KCH) // 72
#define NSTG   4
#define PRE    3
#define MTILE  64
#define NTILES (NPIX / MTILE) // 144
// SMEM map (k_gemm)
#define AB_BYTES 16384                    // 64 x 128 f16 A tile (single buffer)
#define B_OFF    16384
#define B_STB    (NROW * KCH * 2)         // 6144
#define F_OFF    (B_OFF + NSTG * B_STB)   // 40960
#define F_STB    (6 * KCH * 4)            // 3072 (6 feature rows x 128 f32)
#define IF_OFF   (F_OFF + NSTG * F_STB)   // 53248
#define SMEM_DYN (IF_OFF + 6 * MTILE * 4) // 54784  (2+ CTAs/SM)
#define XH     48
#define CONV_SMEM ((NPIX + HDIM * XH + HDIM) * 4)  // 55680 B

// ---------------- device globals ----------------
__device__ float g_feat[NB][6][NPIX];     // 5 scaled features + a = -0.5*l2e*|f|^2
__device__ __half g_smh[2][NB][NROW][NPIX]; // ping-pong softmax (f16)
__device__ float g_u [NB * NC * NPIX];
__device__ float g_sp[NB * NC * NPIX];
__device__ float g_gk[HDIM];
__device__ float g_snrow[HDIM];
__device__ float g_A1[NC * NC];
__device__ float g_A2[NC * NC];

// ---------------- helpers ----------------
__device__ __forceinline__ u32 smem_u32(const void* p) {
    u32 a;
    asm("{ .reg .u64 t; cvta.to.shared.u64 t, %1; cvt.u32.u64 %0, t; }" : "=r"(a) : "l"(p));
    return a;
}
__device__ __forceinline__ void cp16(u32 dst, const void* src) {
    asm volatile("cp.async.cg.shared.global [%0], [%1], 16;" :: "r"(dst), "l"(src) : "memory");
}
__device__ __forceinline__ void ldm_x4(u32 addr, u32& r0, u32& r1, u32& r2, u32& r3) {
    asm volatile("ldmatrix.sync.aligned.m8n8.x4.shared.b16 {%0,%1,%2,%3}, [%4];"
                 : "=r"(r0), "=r"(r1), "=r"(r2), "=r"(r3) : "r"(addr));
}
__device__ __forceinline__ void ldm_x2(u32 addr, u32& r0, u32& r1) {
    asm volatile("ldmatrix.sync.aligned.m8n8.x2.shared.b16 {%0,%1}, [%2];"
                 : "=r"(r0), "=r"(r1) : "r"(addr));
}
__device__ __forceinline__ void mma16816(float* d, u32 a0, u32 a1, u32 a2, u32 a3,
                                         u32 b0, u32 b1) {
    asm volatile(
        "mma.sync.aligned.m16n8k16.row.col.f32.f16.f16.f32 "
        "{%0,%1,%2,%3}, {%4,%5,%6,%7}, {%8,%9}, {%0,%1,%2,%3};"
        : "+f"(d[0]), "+f"(d[1]), "+f"(d[2]), "+f"(d[3])
        : "r"(a0), "r"(a1), "r"(a2), "r"(a3), "r"(b0), "r"(b1));
}
__device__ __forceinline__ u64 ffma2(u64 a, u64 b, u64 c) {
    u64 d; asm("fma.rn.f32x2 %0, %1, %2, %3;" : "=l"(d) : "l"(a), "l"(b), "l"(c)); return d;
}
__device__ __forceinline__ u64 fadd2(u64 a, u64 b) {
    u64 d; asm("add.rn.f32x2 %0, %1, %2;" : "=l"(d) : "l"(a), "l"(b)); return d;
}
__device__ __forceinline__ u64 pk2(float lo, float hi) {
    u64 r; asm("mov.b64 %0, {%1, %2};" : "=l"(r) : "f"(lo), "f"(hi)); return r;
}
__device__ __forceinline__ void upk2(u64 v, float& lo, float& hi) {
    asm("mov.b64 {%0, %1}, %2;" : "=f"(lo), "=f"(hi) : "l"(v));
}
__device__ __forceinline__ float ex2f(float x) {
    float y; asm("ex2.approx.f32 %0, %1;" : "=f"(y) : "f"(x)); return y;
}
// two f32 -> f16x2 (lo -> low half)
__device__ __forceinline__ u32 f2h2(float hi, float lo) {
    u32 r; asm("cvt.rn.f16x2.f32 %0, %1, %2;" : "=r"(r) : "f"(hi), "f"(lo)); return r;
}
__device__ __forceinline__ u64 lds64(u32 addr) {
    u64 v; asm volatile("ld.shared.b64 %0, [%1];" : "=l"(v) : "r"(addr)); return v;
}
__device__ __forceinline__ void sts32(u32 addr, u32 v) {
    asm volatile("st.shared.b32 [%0], %1;" :: "r"(addr), "r"(v));
}

#define L2E 1.4426950408889634f

// ---------------- single merged init kernel ----------------
__global__ __launch_bounds__(256) void k_init(const float* __restrict__ unary,
                                              const float* __restrict__ rgb,
                                              const float* __restrict__ Wsp,
                                              const float* __restrict__ Wbp,
                                              const float* __restrict__ Mp) {
    int tid = threadIdx.x;
    if (blockIdx.x == 0) {
        __shared__ float sgk[HDIM];
        if (tid < HDIM) {
            float v = __expf(-(float)(tid * tid) * (1.0f / 18.0f));
            sgk[tid] = v;
            g_gk[tid] = v;
        }
        __syncthreads();
        if (tid < HDIM) {
            float s = 0.0f;
            for (int y2 = 0; y2 < HDIM; y2++) s += sgk[abs(tid - y2)];
            g_snrow[tid] = s;
        }
        for (int t = tid; t < NC * NC; t += 256) {
            int c = t / NC, c2 = t % NC;
            float a1 = 0.0f, a2 = 0.0f;
            for (int k = 0; k < NC; k++) {
                float m = Mp[c * NC + k];
                a1 += m * Wsp[k * NC + c2];
                a2 += m * Wbp[k * NC + c2];
            }
            g_A1[t] = a1;
            g_A2[t] = a2;
        }
        return;
    }
    int t = (blockIdx.x - 1) * 256 + tid;      // 0 .. NB*NPIX-1
    int b = t / NPIX, n = t % NPIX;
    // per-pixel bilateral features
    {
        const float* rp = rgb + ((size_t)(b * NPIX + n)) * 3;
        float vy = (float)(n / HDIM) * (1.0f / 160.0f);
        float vx = (float)(n % HDIM) * (1.0f / 160.0f);
        float vr = rp[0] * (1.0f / 3.0f);
        float vg = rp[1] * (1.0f / 3.0f);
        float vb = rp[2] * (1.0f / 3.0f);
        float a  = -0.5f * L2E * (vy * vy + vx * vx + vr * vr + vg * vg + vb * vb);
        g_feat[b][0][n] = vy;
        g_feat[b][1][n] = vx;
        g_feat[b][2][n] = vr;
        g_feat[b][3][n] = vg;
        g_feat[b][4][n] = vb;
        g_feat[b][5][n] = a;
    }
    const float* up = unary + ((size_t)(b * NPIX + n)) * NC;
    float v[NC];
    float mx = -1e30f;
#pragma unroll
    for (int c = 0; c < NC; c++) {
        v[c] = up[c];
        g_u[((size_t)(b * NC + c)) * NPIX + n] = v[c];
        mx = fmaxf(mx, v[c]);
    }
    float s = 0.0f;
#pragma unroll
    for (int c = 0; c < NC; c++) { v[c] = __expf(v[c] - mx); s += v[c]; }
    float inv = 1.0f / s;
#pragma unroll
    for (int c = 0; c < NC; c++) g_smh[0][b][c][n] = __float2half(v[c] * inv);
#pragma unroll
    for (int r = NC; r < NROW; r++) {
        __half val = __float2half(r == NC ? 1.0f : 0.0f);
        g_smh[0][b][r][n] = val;
        g_smh[1][b][r][n] = val;
    }
}

// ---------------- fused separable spatial filter, x-half split ----------------
__global__ __launch_bounds__(384) void k_conv(int cur) {
    extern __shared__ float cs[];           // pl[9216] | bl[96*48] | sg[96]
    float* pl = cs;
    float* bl = cs + NPIX;
    float* sg = cs + NPIX + HDIM * XH;
    int tid = threadIdx.x;
    int half = blockIdx.x & 1;
    int plane = blockIdx.x >> 1;
    int c = plane % NC, b = plane / NC;
    const __half* src = &g_smh[cur][b][c][0];
    for (int idx = tid; idx < NPIX; idx += 384) pl[idx] = __half2float(src[idx]);
    if (tid < HDIM) sg[tid] = g_gk[tid];
    __syncthreads();
    int tx = tid % XH;
    int ty = tid / XH;
    int x = half * XH + tx;
    int yb = ty * 12;
    float a[12];
#pragma unroll
    for (int r = 0; r < 12; r++) a[r] = 0.0f;
    for (int xp = 0; xp < HDIM; xp++) {
        float gv = sg[abs(x - xp)];
#pragma unroll
        for (int r = 0; r < 12; r++) a[r] += pl[(yb + r) * HDIM + xp] * gv;
    }
#pragma unroll
    for (int r = 0; r < 12; r++) bl[(yb + r) * XH + tx] = a[r];
    __syncthreads();
#pragma unroll
    for (int r = 0; r < 12; r++) a[r] = 0.0f;
    for (int yp = 0; yp < HDIM; yp++) {
        float v = bl[yp * XH + tx];
#pragma unroll
        for (int r = 0; r < 12; r++) a[r] += v * sg[abs(yb + r - yp)];
    }
    float* out = g_sp + (size_t)(b * NC + c) * NPIX;
#pragma unroll
    for (int r = 0; r < 12; r++) out[(yb + r) * HDIM + x] = a[r];
}

// ---------------- stage loader: B tile + j-features via cp.async ----------------
__device__ __forceinline__ void load_chunk(u32 sb, int st, int jb,
                                           const float* featb,
                                           const __half* bh, int tid) {
    u32 bb = sb + B_OFF + st * B_STB;
    {
        int r = tid >> 4, u = tid & 15;        // B rows 0..15
        cp16(bb + r * 256 + ((u ^ (r & 7)) << 4),
             (const char*)(bh + (size_t)r * NPIX + jb) + u * 16);
    }
    if (tid < (NROW - 16) * 16) {              // B rows 16..23
        int t = tid + 256;
        int r = t >> 4, u = t & 15;
        cp16(bb + r * 256 + ((u ^ (r & 7)) << 4),
             (const char*)(bh + (size_t)r * NPIX + jb) + u * 16);
    }
    if (tid < 192) {                           // feat: 6 rows x 32 units (512 B each)
        int k = tid >> 5, u = tid & 31;
        cp16(sb + F_OFF + st * F_STB + k * 512 + u * 16,
             (const char*)(featb + (size_t)k * NPIX + jb) + u * 16);
    }
    asm volatile("cp.async.commit_group;" ::: "memory");
}

// ---------------- fused build+GEMM: compute f16 A tile on the fly, HMMA, epilogue ----------------
__global__ __launch_bounds__(256, 2) void k_gemm(int cur, int last, float* __restrict__ outp) {
    extern __shared__ __align__(1024) char smem[];
    __shared__ float sA1[NC * NC], sA2[NC * NC];

    int tid  = threadIdx.x;
    int warp = tid >> 5, lane = tid & 31;
    int b    = blockIdx.y;
    int i0   = blockIdx.x * MTILE;
    u32 sb   = smem_u32(smem);
    int nxt  = cur ^ 1;
    int hi   = warp >> 2;          // 0: n-rows 0-15, 1: n-rows 16-23

    for (int i = tid; i < NC * NC; i += 256) { sA1[i] = g_A1[i]; sA2[i] = g_A2[i]; }

    const float* featb = &g_feat[b][0][0];
    const __half* bh = &g_smh[cur][b][0][0];

    // i-row features -> SMEM [k][64]
    float* sif = (float*)(smem + IF_OFF);
    for (int t = tid; t < 6 * MTILE; t += 256) {
        int k = t >> 6, r = t & 63;
        sif[k * MTILE + r] = featb[(size_t)k * NPIX + i0 + r];
    }

    // prologue
#pragma unroll
    for (int s = 0; s < PRE; s++) load_chunk(sb, s, s * KCH, featb, bh, tid);

    float acc[2][4];
#pragma unroll
    for (int nt = 0; nt < 2; nt++)
#pragma unroll
        for (int r = 0; r < 4; r++) acc[nt][r] = 0.0f;

    int a_row = (warp & 3) * 16 + ((lane >> 3) & 1) * 8 + (lane & 7);
    int a_ku  = lane >> 4;
    int b_n   = hi ? (16 + (lane & 7)) : (((lane >> 4) & 1) * 8 + (lane & 7));
    int b_ku  = (lane >> 3) & 1;
    int a_sw  = a_row & 7;

    // compute-store geometry: lane covers j pairs (2l,2l+1) and (64+2l,64+2l+1)
    u32 st_off0 = ((u32)(lane >> 2) << 4);         // unit l>>2 (pre-swizzle)
    u32 st_off1 = ((u32)(8 + (lane >> 2)) << 4);
    u32 st_sub  = ((u32)(lane & 3) << 2);

    for (int ch = 0; ch < NCHUNKS; ch++) {
        int st = ch & (NSTG - 1);
        if (ch < NCHUNKS - 2)       asm volatile("cp.async.wait_group 2;" ::: "memory");
        else if (ch == NCHUNKS - 2) asm volatile("cp.async.wait_group 1;" ::: "memory");
        else                        asm volatile("cp.async.wait_group 0;" ::: "memory");
        __syncthreads();                            // stage ready; prev MMA reads of ABUF done
        if (ch + PRE < NCHUNKS)
            load_chunk(sb, (ch + PRE) & (NSTG - 1), (ch + PRE) * KCH, featb, bh, tid);

        // ---- compute A tile rows warp*8 .. warp*8+7 ----
        {
            u32 fb = sb + F_OFF + st * F_STB + ((u32)lane << 3);   // +2l floats
            u64 fj0[6], fj1[6];
#pragma unroll
            for (int k = 0; k < 6; k++) {
                fj0[k] = lds64(fb + k * 512);
                fj1[k] = lds64(fb + k * 512 + 256);
            }
#pragma unroll
            for (int r = 0; r < 8; r++) {
                int row = warp * 8 + r;
                float f0 = sif[0 * MTILE + row], f1 = sif[1 * MTILE + row];
                float f2 = sif[2 * MTILE + row], f3 = sif[3 * MTILE + row];
                float f4 = sif[4 * MTILE + row], f5 = sif[5 * MTILE + row];
                u64 g0 = pk2(L2E * f0, L2E * f0);
                u64 g1 = pk2(L2E * f1, L2E * f1);
                u64 g2 = pk2(L2E * f2, L2E * f2);
                u64 g3 = pk2(L2E * f3, L2E * f3);
                u64 g4 = pk2(L2E * f4, L2E * f4);
                u64 ai = pk2(f5, f5);
                u32 base = sb + row * 256;
                u32 swz = ((u32)(row & 7) << 4);
                u64 acc0 = fadd2(ai, fj0[5]);
                acc0 = ffma2(g0, fj0[0], acc0);
                acc0 = ffma2(g1, fj0[1], acc0);
                acc0 = ffma2(g2, fj0[2], acc0);
                acc0 = ffma2(g3, fj0[3], acc0);
                acc0 = ffma2(g4, fj0[4], acc0);
                u64 acc1 = fadd2(ai, fj1[5]);
                acc1 = ffma2(g0, fj1[0], acc1);
                acc1 = ffma2(g1, fj1[1], acc1);
                acc1 = ffma2(g2, fj1[2], acc1);
                acc1 = ffma2(g3, fj1[3], acc1);
                acc1 = ffma2(g4, fj1[4], acc1);
                float e0, e1, e2, e3;
                upk2(acc0, e0, e1);
                upk2(acc1, e2, e3);
                sts32(base + (st_off0 ^ swz) + st_sub, f2h2(ex2f(e1), ex2f(e0)));
                sts32(base + (st_off1 ^ swz) + st_sub, f2h2(ex2f(e3), ex2f(e2)));
            }
        }
        __syncthreads();                            // A tile complete

        // ---- HMMA over ABUF + B stage ----
        u32 a_base = sb + a_row * 256;
        u32 b_base = sb + B_OFF + st * B_STB + b_n * 256;
        int b_sw = b_n & 7;

        if (hi == 0) {
#pragma unroll
            for (int kk = 0; kk < 8; kk++) {
                u32 a0, a1, a2, a3, p0, p1, p2, p3;
                ldm_x4(a_base + (((kk * 2 + a_ku) ^ a_sw) << 4), a0, a1, a2, a3);
                ldm_x4(b_base + (((kk * 2 + b_ku) ^ b_sw) << 4), p0, p1, p2, p3);
                mma16816(acc[0], a0, a1, a2, a3, p0, p1);
                mma16816(acc[1], a0, a1, a2, a3, p2, p3);
            }
        } else {
#pragma unroll
            for (int kk = 0; kk < 8; kk++) {
                u32 a0, a1, a2, a3, q0, q1;
                ldm_x4(a_base + (((kk * 2 + a_ku) ^ a_sw) << 4), a0, a1, a2, a3);
                ldm_x2(b_base + (((kk * 2 + b_ku) ^ b_sw) << 4), q0, q1);
                mma16816(acc[0], a0, a1, a2, a3, q0, q1);
            }
        }
    }

    // ---- transpose accumulators to smem [64 rows x 33] ----
    __syncthreads();
    float* tr = (float*)smem;
    {
        int r0 = (warp & 3) * 16 + (lane >> 2);
        int cb = (lane & 3) * 2;
        if (hi == 0) {
#pragma unroll
            for (int nt = 0; nt < 2; nt++) {
                tr[r0 * 33 + nt * 8 + cb]            = acc[nt][0];
                tr[r0 * 33 + nt * 8 + cb + 1]        = acc[nt][1];
                tr[(r0 + 8) * 33 + nt * 8 + cb]      = acc[nt][2];
                tr[(r0 + 8) * 33 + nt * 8 + cb + 1]  = acc[nt][3];
            }
        } else {
            tr[r0 * 33 + 16 + cb]            = acc[0][0];
            tr[r0 * 33 + 16 + cb + 1]        = acc[0][1];
            tr[(r0 + 8) * 33 + 16 + cb]      = acc[0][2];
            tr[(r0 + 8) * 33 + 16 + cb + 1]  = acc[0][3];
        }
    }
    __syncthreads();

    // ---- epilogue: threads 0-63, one pixel each ----
    if (tid < MTILE) {
        const float* row = tr + tid * 33;
        int i = i0 + tid;
        float inv_bn = 1.0f / row[NC];                    // ones channel
        float inv_sn = 1.0f / (g_snrow[i / HDIM] * g_snrow[i % HDIM]);
        float spv[NC], blv[NC];
        const float* spp = g_sp + (size_t)b * NC * NPIX + i;
#pragma unroll
        for (int c = 0; c < NC; c++) {
            spv[c] = spp[c * NPIX] * inv_sn;
            blv[c] = row[c] * inv_bn;
        }
        const float* up = g_u + (size_t)b * NC * NPIX + i;
        float qv[NC];
        float mx = -1e30f;
        for (int c = 0; c < NC; c++) {
            float a = up[c * NPIX];
#pragma unroll
            for (int c2 = 0; c2 < NC; c2++)
                a -= sA1[c * NC + c2] * spv[c2] + sA2[c * NC + c2] * blv[c2];
            qv[c] = a;
            mx = fmaxf(mx, a);
        }
        if (last) {
            float* op = outp + ((size_t)(b * NPIX + i)) * NC;
#pragma unroll
            for (int c = 0; c < NC; c++) op[c] = qv[c];
        } else {
            float s = 0.0f;
#pragma unroll
            for (int c = 0; c < NC; c++) { qv[c] = __expf(qv[c] - mx); s += qv[c]; }
            float inv = 1.0f / s;
#pragma unroll
            for (int c = 0; c < NC; c++)
                g_smh[nxt][b][c][i] = __float2half(qv[c] * inv);
        }
    }
}

// ---------------- launch ----------------
extern "C" void kernel_launch(void* const* d_in, const int* in_sizes, int n_in,
                              void* d_out, int out_size) {
    const float* unary = (const float*)d_in[0];
    const float* rgb   = (const float*)d_in[1];
    const float* Wsp   = (const float*)d_in[2];
    const float* Wbp   = (const float*)d_in[3];
    const float* Mp    = (const float*)d_in[4];

    cudaFuncSetAttribute(k_gemm, cudaFuncAttributeMaxDynamicSharedMemorySize, SMEM_DYN);
    cudaFuncSetAttribute(k_conv, cudaFuncAttributeMaxDynamicSharedMemorySize, CONV_SMEM);

    k_init<<<1 + NB * NPIX / 256, 256>>>(unary, rgb, Wsp, Wbp, Mp);

    for (int it = 0; it < 5; it++) {
        int cur = it & 1;
        k_conv<<<NB * NC * 2, 384, CONV_SMEM>>>(cur);
        k_gemm<<<dim3(NTILES, NB), 256, SMEM_DYN>>>(cur, it == 4, (float*)d_out);
    }
}

// round 17
// speedup vs baseline: 1.4580x; 1.4580x over previous
#include <cuda_runtime.h>
#include <cuda_bf16.h>
#include <cstdint>

typedef unsigned int u32;
typedef unsigned long long u64;

#define HDIM   96
#define NPIX   9216
#define NC     21
#define NROW   24            // padded B rows: 21 classes + ones + 2 zero
#define NB     2
#define KCH    128           // K (j) per pipeline stage
#define NCHUNKS (NPIX / KCH) // 72
#define NSTG   4
#define MTILE  64
#define NTILES (NPIX / MTILE) // 144
#define A_STB  (MTILE * KCH * 2)   // 16384 B per stage
#define B_STB  (NROW  * KCH * 2)   // 6144 B per stage
#define SMEM_B_OFF (NSTG * A_STB)               // 65536
#define SMEM_DYN   (SMEM_B_OFF + NSTG * B_STB)  // 90112 B  (2 CTAs/SM)
#define XQ     24                                // x-quarter width
#define PLS    97                                // padded pl row stride
#define BLS    25                                // padded bl row stride
#define CONV_SMEM ((HDIM * PLS + HDIM * BLS + HDIM) * 4)  // 47232 B

// ---------------- device globals ----------------
// Kb row-major [b][j][i] (symmetric -> rows double as K-major A panels)
__device__ __nv_bfloat16 g_Kbh[(size_t)NB * NPIX * NPIX]; // 340 MB
__device__ __nv_bfloat16 g_smh[2][NB][NROW][NPIX];        // ping-pong softmax (bf16)
__device__ float g_u [NB * NC * NPIX];
__device__ float g_sp[NB * NC * NPIX];
__device__ float g_gk[HDIM];
__device__ float g_snrow[HDIM];
__device__ float g_A1[NC * NC];
__device__ float g_A2[NC * NC];

// ---------------- helpers ----------------
__device__ __forceinline__ u32 smem_u32(const void* p) {
    u32 a;
    asm("{ .reg .u64 t; cvta.to.shared.u64 t, %1; cvt.u32.u64 %0, t; }" : "=r"(a) : "l"(p));
    return a;
}
__device__ __forceinline__ void cp16(u32 dst, const void* src) {
    asm volatile("cp.async.cg.shared.global [%0], [%1], 16;" :: "r"(dst), "l"(src) : "memory");
}
__device__ __forceinline__ void ldm_x4(u32 addr, u32& r0, u32& r1, u32& r2, u32& r3) {
    asm volatile("ldmatrix.sync.aligned.m8n8.x4.shared.b16 {%0,%1,%2,%3}, [%4];"
                 : "=r"(r0), "=r"(r1), "=r"(r2), "=r"(r3) : "r"(addr));
}
__device__ __forceinline__ void ldm_x2(u32 addr, u32& r0, u32& r1) {
    asm volatile("ldmatrix.sync.aligned.m8n8.x2.shared.b16 {%0,%1}, [%2];"
                 : "=r"(r0), "=r"(r1) : "r"(addr));
}
__device__ __forceinline__ void mma16816(float* d, u32 a0, u32 a1, u32 a2, u32 a3,
                                         u32 b0, u32 b1) {
    asm volatile(
        "mma.sync.aligned.m16n8k16.row.col.f32.bf16.bf16.f32 "
        "{%0,%1,%2,%3}, {%4,%5,%6,%7}, {%8,%9}, {%0,%1,%2,%3};"
        : "+f"(d[0]), "+f"(d[1]), "+f"(d[2]), "+f"(d[3])
        : "r"(a0), "r"(a1), "r"(a2), "r"(a3), "r"(b0), "r"(b1));
}

// packed f32x2 helpers (build kernel)
__device__ __forceinline__ u64 ffma2(u64 a, u64 b, u64 c) {
    u64 d; asm("fma.rn.f32x2 %0, %1, %2, %3;" : "=l"(d) : "l"(a), "l"(b), "l"(c)); return d;
}
__device__ __forceinline__ u64 fadd2(u64 a, u64 b) {
    u64 d; asm("add.rn.f32x2 %0, %1, %2;" : "=l"(d) : "l"(a), "l"(b)); return d;
}
__device__ __forceinline__ u64 pk2(float lo, float hi) {
    u64 r; asm("mov.b64 %0, {%1, %2};" : "=l"(r) : "f"(lo), "f"(hi)); return r;
}
__device__ __forceinline__ void upk2(u64 v, float& lo, float& hi) {
    asm("mov.b64 {%0, %1}, %2;" : "=f"(lo), "=f"(hi) : "l"(v));
}
__device__ __forceinline__ float ex2f(float x) {
    float y; asm("ex2.approx.f32 %0, %1;" : "=f"(y) : "f"(x)); return y;
}
__device__ __forceinline__ u32 f2bf2(float hi, float lo) {
    u32 r; asm("cvt.rn.bf16x2.f32 %0, %1, %2;" : "=r"(r) : "f"(hi), "f"(lo)); return r;
}

#define L2E 1.4426950408889634f

// ---------------- single merged init kernel ----------------
__global__ __launch_bounds__(256) void k_init(const float* __restrict__ unary,
                                              const float* __restrict__ Wsp,
                                              const float* __restrict__ Wbp,
                                              const float* __restrict__ Mp) {
    int tid = threadIdx.x;
    if (blockIdx.x == 0) {
        __shared__ float sgk[HDIM];
        if (tid < HDIM) {
            float v = __expf(-(float)(tid * tid) * (1.0f / 18.0f));
            sgk[tid] = v;
            g_gk[tid] = v;
        }
        __syncthreads();
        if (tid < HDIM) {
            float s = 0.0f;
            for (int y2 = 0; y2 < HDIM; y2++) s += sgk[abs(tid - y2)];
            g_snrow[tid] = s;
        }
        for (int t = tid; t < NC * NC; t += 256) {
            int c = t / NC, c2 = t % NC;
            float a1 = 0.0f, a2 = 0.0f;
            for (int k = 0; k < NC; k++) {
                float m = Mp[c * NC + k];
                a1 += m * Wsp[k * NC + c2];
                a2 += m * Wbp[k * NC + c2];
            }
            g_A1[t] = a1;
            g_A2[t] = a2;
        }
        return;
    }
    int t = (blockIdx.x - 1) * 256 + tid;      // 0 .. NB*NPIX-1
    int b = t / NPIX, n = t % NPIX;
    const float* up = unary + ((size_t)(b * NPIX + n)) * NC;
    float v[NC];
    float mx = -1e30f;
#pragma unroll
    for (int c = 0; c < NC; c++) {
        v[c] = up[c];
        g_u[((size_t)(b * NC + c)) * NPIX + n] = v[c];
        mx = fmaxf(mx, v[c]);
    }
    float s = 0.0f;
#pragma unroll
    for (int c = 0; c < NC; c++) { v[c] = __expf(v[c] - mx); s += v[c]; }
    float inv = 1.0f / s;
#pragma unroll
    for (int c = 0; c < NC; c++) g_smh[0][b][c][n] = __float2bfloat16(v[c] * inv);
#pragma unroll
    for (int r = NC; r < NROW; r++) {
        __nv_bfloat16 val = __float2bfloat16(r == NC ? 1.0f : 0.0f);
        g_smh[0][b][r][n] = val;
        g_smh[1][b][r][n] = val;
    }
}

// ---------------- build dense bilateral kernel ----------------
// arg = ai + aj + sum_k (l2e*fi_k)*fj_k ;  ai = -0.5*l2e*|fi|^2 (same for j)
__global__ __launch_bounds__(256) void k_build(const float* __restrict__ rgb) {
    __shared__ u64 snj[6][32];     // fj (5 features, duplicated) + aj (duplicated)
    int b  = blockIdx.z;
    int i0 = (blockIdx.x * 256 + threadIdx.x) * 2;
    int j0 = blockIdx.y * 32;
    if (threadIdx.x < 32) {
        int j = j0 + threadIdx.x;
        const float* rp = rgb + ((size_t)(b * NPIX + j)) * 3;
        float vy = (float)(j / HDIM) * (1.0f / 160.0f);
        float vx = (float)(j % HDIM) * (1.0f / 160.0f);
        float vr = rp[0] * (1.0f / 3.0f);
        float vg = rp[1] * (1.0f / 3.0f);
        float vb = rp[2] * (1.0f / 3.0f);
        float aj = -0.5f * L2E * (vy * vy + vx * vx + vr * vr + vg * vg + vb * vb);
        snj[0][threadIdx.x] = pk2(vy, vy);
        snj[1][threadIdx.x] = pk2(vx, vx);
        snj[2][threadIdx.x] = pk2(vr, vr);
        snj[3][threadIdx.x] = pk2(vg, vg);
        snj[4][threadIdx.x] = pk2(vb, vb);
        snj[5][threadIdx.x] = pk2(aj, aj);
    }
    __syncthreads();
    const float* rp0 = rgb + ((size_t)(b * NPIX + i0)) * 3;
    float wy0 = (float)(i0 / HDIM) * (1.0f / 160.0f), wy1 = (float)((i0 + 1) / HDIM) * (1.0f / 160.0f);
    float wx0 = (float)(i0 % HDIM) * (1.0f / 160.0f), wx1 = (float)((i0 + 1) % HDIM) * (1.0f / 160.0f);
    float wr0 = rp0[0] * (1.0f / 3.0f), wr1 = rp0[3] * (1.0f / 3.0f);
    float wg0 = rp0[1] * (1.0f / 3.0f), wg1 = rp0[4] * (1.0f / 3.0f);
    float wb0 = rp0[2] * (1.0f / 3.0f), wb1 = rp0[5] * (1.0f / 3.0f);
    float ai0 = -0.5f * L2E * (wy0 * wy0 + wx0 * wx0 + wr0 * wr0 + wg0 * wg0 + wb0 * wb0);
    float ai1 = -0.5f * L2E * (wy1 * wy1 + wx1 * wx1 + wr1 * wr1 + wg1 * wg1 + wb1 * wb1);
    u64 gy = pk2(L2E * wy0, L2E * wy1);
    u64 gx = pk2(L2E * wx0, L2E * wx1);
    u64 gr = pk2(L2E * wr0, L2E * wr1);
    u64 gg = pk2(L2E * wg0, L2E * wg1);
    u64 gb = pk2(L2E * wb0, L2E * wb1);
    u64 ai2 = pk2(ai0, ai1);
    __nv_bfloat16* out = g_Kbh + (size_t)b * NPIX * NPIX + (size_t)j0 * NPIX + i0;
#pragma unroll 4
    for (int jj = 0; jj < 32; jj++) {
        u64 acc = fadd2(ai2, snj[5][jj]);
        acc = ffma2(gy, snj[0][jj], acc);
        acc = ffma2(gx, snj[1][jj], acc);
        acc = ffma2(gr, snj[2][jj], acc);
        acc = ffma2(gg, snj[3][jj], acc);
        acc = ffma2(gb, snj[4][jj], acc);
        float a0, a1; upk2(acc, a0, a1);
        *reinterpret_cast<u32*>(out + (size_t)jj * NPIX) = f2bf2(ex2f(a1), ex2f(a0));
    }
}

// ---------------- fused separable spatial filter, x-quarter split ----------------
// grid: NB*NC*4 blocks (plane, x-quarter); block 192 = (24 x-local) x (8 y-groups)
// padded SMEM strides (97 / 25) keep all LDS conflict-free across y-groups.
__global__ __launch_bounds__(192) void k_conv(int cur) {
    extern __shared__ float cs[];           // pl[96*97] | bl[96*25] | sg[96]
    float* pl = cs;
    float* bl = cs + HDIM * PLS;
    float* sg = cs + HDIM * PLS + HDIM * BLS;
    int tid = threadIdx.x;
    int quarter = blockIdx.x & 3;
    int plane = blockIdx.x >> 2;
    int c = plane % NC, b = plane / NC;
    const __nv_bfloat16* src = &g_smh[cur][b][c][0];
    for (int idx = tid; idx < NPIX; idx += 192) {
        int row = idx / HDIM, col = idx - row * HDIM;
        pl[row * PLS + col] = __bfloat162float(src[idx]);
    }
    if (tid < HDIM) sg[tid] = g_gk[tid];
    __syncthreads();
    int tx = tid % XQ;                      // x-local 0..23
    int ty = tid / XQ;                      // 0..7
    int x = quarter * XQ + tx;
    int yb = ty * 12;
    float a[12];
    // x-pass: bl[y][tx] = sum_xp pl[y][xp] * g[|x-xp|]   for y in [yb, yb+12)
#pragma unroll
    for (int r = 0; r < 12; r++) a[r] = 0.0f;
    for (int xp = 0; xp < HDIM; xp++) {
        float gv = sg[abs(x - xp)];
#pragma unroll
        for (int r = 0; r < 12; r++) a[r] += pl[(yb + r) * PLS + xp] * gv;
    }
#pragma unroll
    for (int r = 0; r < 12; r++) bl[(yb + r) * BLS + tx] = a[r];
    __syncthreads();
    // y-pass: sp[yo][x] = sum_yp bl[yp][tx] * g[|yo-yp|]  for yo in [yb, yb+12)
#pragma unroll
    for (int r = 0; r < 12; r++) a[r] = 0.0f;
    for (int yp = 0; yp < HDIM; yp++) {
        float v = bl[yp * BLS + tx];
#pragma unroll
        for (int r = 0; r < 12; r++) a[r] += v * sg[abs(yb + r - yp)];
    }
    float* out = g_sp + (size_t)(b * NC + c) * NPIX;
#pragma unroll
    for (int r = 0; r < 12; r++) out[(yb + r) * HDIM + x] = a[r];
}

// ---------------- stage loader: gmem -> swizzled smem via cp.async ----------------
__device__ __forceinline__ void load_chunk(u32 sb, int st, int jb,
                                           const __nv_bfloat16* kb,
                                           const __nv_bfloat16* bh, int tid) {
    u32 ab = sb + st * A_STB;
#pragma unroll
    for (int v = 0; v < 4; v++) {              // A: 64 rows x 16 x 16B
        int t = tid + v * 256;
        int r = t >> 4, u = t & 15;
        cp16(ab + r * 256 + ((u ^ (r & 7)) << 4),
             (const char*)(kb + (size_t)r * NPIX + jb) + u * 16);
    }
    u32 bb = sb + SMEM_B_OFF + st * B_STB;
    {
        int t = tid;                           // B rows 0..15
        int r = t >> 4, u = t & 15;
        cp16(bb + r * 256 + ((u ^ (r & 7)) << 4),
             (const char*)(bh + (size_t)r * NPIX + jb) + u * 16);
    }
    if (tid < (NROW - 16) * 16) {              // B rows 16..23
        int t = tid + 256;
        int r = t >> 4, u = t & 15;
        cp16(bb + r * 256 + ((u ^ (r & 7)) << 4),
             (const char*)(bh + (size_t)r * NPIX + jb) + u * 16);
    }
    asm volatile("cp.async.commit_group;" ::: "memory");
}

// ---------------- HMMA GEMM (M=64, 2 CTAs/SM), single-barrier load-first pipeline ----------------
__global__ __launch_bounds__(256, 2) void k_gemm(int cur, int last, float* __restrict__ outp) {
    extern __shared__ __align__(1024) char smem[];
    __shared__ float sA1[NC * NC], sA2[NC * NC];

    int tid  = threadIdx.x;
    int warp = tid >> 5, lane = tid & 31;
    int b    = blockIdx.y;
    int i0   = blockIdx.x * MTILE;
    u32 sb   = smem_u32(smem);
    int nxt  = cur ^ 1;
    int hi   = warp >> 2;          // 0: n-rows 0-15, 1: n-rows 16-23

    for (int i = tid; i < NC * NC; i += 256) { sA1[i] = g_A1[i]; sA2[i] = g_A2[i]; }

    const __nv_bfloat16* kb = g_Kbh + (size_t)b * NPIX * NPIX + (size_t)i0 * NPIX; // symmetric
    const __nv_bfloat16* bh = &g_smh[cur][b][0][0];

    // prologue: 3 chunks in flight
    load_chunk(sb, 0, 0 * KCH, kb, bh, tid);
    load_chunk(sb, 1, 1 * KCH, kb, bh, tid);
    load_chunk(sb, 2, 2 * KCH, kb, bh, tid);

    float acc[2][4];
#pragma unroll
    for (int nt = 0; nt < 2; nt++)
#pragma unroll
        for (int r = 0; r < 4; r++) acc[nt][r] = 0.0f;

    int a_row = (warp & 3) * 16 + ((lane >> 3) & 1) * 8 + (lane & 7);
    int a_ku  = lane >> 4;
    int b_n   = hi ? (16 + (lane & 7)) : (((lane >> 4) & 1) * 8 + (lane & 7));
    int b_ku  = (lane >> 3) & 1;

    for (int ch = 0; ch < NCHUNKS; ch++) {
        int st = ch & (NSTG - 1);
        if (ch < NCHUNKS - 2)       asm volatile("cp.async.wait_group 2;" ::: "memory");
        else if (ch == NCHUNKS - 2) asm volatile("cp.async.wait_group 1;" ::: "memory");
        else                        asm volatile("cp.async.wait_group 0;" ::: "memory");
        __syncthreads();
        // issue next load FIRST (stage (ch+3)&3 = (ch-1)&3, fully consumed before this barrier)
        if (ch + 3 < NCHUNKS) load_chunk(sb, (ch + 3) & (NSTG - 1), (ch + 3) * KCH, kb, bh, tid);

        u32 a_base = sb + st * A_STB + a_row * 256;
        u32 b_base = sb + SMEM_B_OFF + st * B_STB + b_n * 256;
        int a_sw = a_row & 7, b_sw = b_n & 7;

        if (hi == 0) {
#pragma unroll
            for (int kk = 0; kk < 8; kk++) {
                u32 a0, a1, a2, a3, p0, p1, p2, p3;
                ldm_x4(a_base + (((kk * 2 + a_ku) ^ a_sw) << 4), a0, a1, a2, a3);
                ldm_x4(b_base + (((kk * 2 + b_ku) ^ b_sw) << 4), p0, p1, p2, p3);
                mma16816(acc[0], a0, a1, a2, a3, p0, p1);
                mma16816(acc[1], a0, a1, a2, a3, p2, p3);
            }
        } else {
#pragma unroll
            for (int kk = 0; kk < 8; kk++) {
                u32 a0, a1, a2, a3, q0, q1;
                ldm_x4(a_base + (((kk * 2 + a_ku) ^ a_sw) << 4), a0, a1, a2, a3);
                ldm_x2(b_base + (((kk * 2 + b_ku) ^ b_sw) << 4), q0, q1);
                mma16816(acc[0], a0, a1, a2, a3, q0, q1);
            }
        }
    }

    // ---- transpose accumulators to smem [64 rows x 33] ----
    __syncthreads();
    float* tr = (float*)smem;
    {
        int r0 = (warp & 3) * 16 + (lane >> 2);
        int cb = (lane & 3) * 2;
        if (hi == 0) {
#pragma unroll
            for (int nt = 0; nt < 2; nt++) {
                tr[r0 * 33 + nt * 8 + cb]            = acc[nt][0];
                tr[r0 * 33 + nt * 8 + cb + 1]        = acc[nt][1];
                tr[(r0 + 8) * 33 + nt * 8 + cb]      = acc[nt][2];
                tr[(r0 + 8) * 33 + nt * 8 + cb + 1]  = acc[nt][3];
            }
        } else {
            tr[r0 * 33 + 16 + cb]            = acc[0][0];
            tr[r0 * 33 + 16 + cb + 1]        = acc[0][1];
            tr[(r0 + 8) * 33 + 16 + cb]      = acc[0][2];
            tr[(r0 + 8) * 33 + 16 + cb + 1]  = acc[0][3];
        }
    }
    __syncthreads();

    // ---- epilogue: threads 0-63, one pixel each ----
    if (tid < MTILE) {
        const float* row = tr + tid * 33;
        int i = i0 + tid;
        float inv_bn = 1.0f / row[NC];                    // ones channel
        float inv_sn = 1.0f / (g_snrow[i / HDIM] * g_snrow[i % HDIM]);
        float spv[NC], blv[NC];
        const float* spp = g_sp + (size_t)b * NC * NPIX + i;
#pragma unroll
        for (int c = 0; c < NC; c++) {
            spv[c] = spp[c * NPIX] * inv_sn;
            blv[c] = row[c] * inv_bn;
        }
        const float* up = g_u + (size_t)b * NC * NPIX + i;
        float qv[NC];
        float mx = -1e30f;
        for (int c = 0; c < NC; c++) {
            float a = up[c * NPIX];
#pragma unroll
            for (int c2 = 0; c2 < NC; c2++)
                a -= sA1[c * NC + c2] * spv[c2] + sA2[c * NC + c2] * blv[c2];
            qv[c] = a;
            mx = fmaxf(mx, a);
        }
        if (last) {
            float* op = outp + ((size_t)(b * NPIX + i)) * NC;
#pragma unroll
            for (int c = 0; c < NC; c++) op[c] = qv[c];
        } else {
            float s = 0.0f;
#pragma unroll
            for (int c = 0; c < NC; c++) { qv[c] = __expf(qv[c] - mx); s += qv[c]; }
            float inv = 1.0f / s;
#pragma unroll
            for (int c = 0; c < NC; c++)
                g_smh[nxt][b][c][i] = __float2bfloat16(qv[c] * inv);
        }
    }
}

// ---------------- launch ----------------
extern "C" void kernel_launch(void* const* d_in, const int* in_sizes, int n_in,
                              void* d_out, int out_size) {
    const float* unary = (const float*)d_in[0];
    const float* rgb   = (const float*)d_in[1];
    const float* Wsp   = (const float*)d_in[2];
    const float* Wbp   = (const float*)d_in[3];
    const float* Mp    = (const float*)d_in[4];

    cudaFuncSetAttribute(k_gemm, cudaFuncAttributeMaxDynamicSharedMemorySize, SMEM_DYN);
    cudaFuncSetAttribute(k_conv, cudaFuncAttributeMaxDynamicSharedMemorySize, CONV_SMEM);

    k_init<<<1 + NB * NPIX / 256, 256>>>(unary, Wsp, Wbp, Mp);
    k_build<<<dim3(NPIX / 512, NPIX / 32, NB), 256>>>(rgb);

    for (int it = 0; it < 5; it++) {
        int cur = it & 1;
        k_conv<<<NB * NC * 4, 192, CONV_SMEM>>>(cur);
        k_gemm<<<dim3(NTILES, NB), 256, SMEM_DYN>>>(cur, it == 4, (float*)d_out);
    }
}